// round 6
// baseline (speedup 1.0000x reference)
#include <cuda_runtime.h>

#define NN 20000
#define BB 64
#define EE 1280000
#define TNB 625    // NN / 32 (exact)

// Scratch (allocation-free per rules).
__device__ __align__(16) float g_xT[NN * BB];    // xT[n*64 + b]
__device__ __align__(16) float g_accT[NN * BB];  // accT[n*64 + b]

// K1: smem-tiled transpose x[B,N] -> xT[N,B], 32n x 64b tiles, 512 threads,
// one float4 work item per thread per phase (grid=625 for latency hiding).
// Also zeroes this block's accT slice. NN % 32 == 0: no bounds checks.
__global__ void __launch_bounds__(512)
prep_kernel(const float* __restrict__ x) {
    __shared__ float t[32][65];
    int tid = threadIdx.x;
    int n0 = blockIdx.x * 32;

    const float4* x4 = (const float4*)x;

    // Phase A: coalesced float4 reads along n. 64 b x 8 q = 512 items.
    {
        int b = tid >> 3, q = tid & 7;
        float4 v = x4[b * (NN / 4) + (n0 >> 2) + q];
        int nc = 4 * q;
        t[nc + 0][b] = v.x;
        t[nc + 1][b] = v.y;
        t[nc + 2][b] = v.z;
        t[nc + 3][b] = v.w;
    }
    __syncthreads();

    // Phase B: coalesced float4 writes along b. 32 nc x 16 bq = 512 items.
    {
        float4* xT4  = (float4*)g_xT;
        float4* acc4 = (float4*)g_accT;
        int nc = tid >> 4, bq = tid & 15;
        int n = n0 + nc;
        float4 v;
        v.x = t[nc][4 * bq + 0];
        v.y = t[nc][4 * bq + 1];
        v.z = t[nc][4 * bq + 2];
        v.w = t[nc][4 * bq + 3];
        xT4[n * 16 + bq]  = v;
        acc4[n * 16 + bq] = make_float4(0.f, 0.f, 0.f, 0.f);
    }
}

// K2: edge scatter, half-warp per edge (unchanged — at LTS byte cap).
// Per edge: one LDG.128 gather from L2-resident xT + one red.global.add.v4.f32.
__global__ void scatter_kernel(const float* __restrict__ adj,
                               const float* __restrict__ w,
                               const int* __restrict__ src,
                               const int* __restrict__ dst) {
    int g = (blockIdx.x * blockDim.x + threadIdx.x) >> 5;  // warp id
    int lane = threadIdx.x & 31;
    int e = g * 32 + lane;
    if (e >= EE) return;  // EE % 32 == 0: whole warp exits together

    int   s = src[e];
    int   d = dst[e];
    float v = adj[e] * w[e];

    int half = lane >> 4;
    int ll   = lane & 15;

    const float4* xT4 = (const float4*)g_xT;

    #pragma unroll 1
    for (int j = 0; j < 16; j++) {
        int sel = 2 * j + half;
        int   sj = __shfl_sync(0xffffffffu, s, sel);
        int   dj = __shfl_sync(0xffffffffu, d, sel);
        float vj = __shfl_sync(0xffffffffu, v, sel);

        float4 xv = xT4[sj * 16 + ll];           // LDG.128, coalesced, L2-hit
        float4 r;
        r.x = vj * xv.x;  r.y = vj * xv.y;
        r.z = vj * xv.z;  r.w = vj * xv.w;

        float* accp = &g_accT[dj * 64 + 4 * ll]; // 16B-aligned
        asm volatile("red.global.add.v4.f32 [%0], {%1, %2, %3, %4};"
                     :: "l"(accp), "f"(r.x), "f"(r.y), "f"(r.z), "f"(r.w)
                     : "memory");
    }
}

// K3: epilogue. Tile-transpose accT [N,B] -> out [B,N], 32n x 64b tiles,
// 512 threads, one float4 item per thread per phase.
// out = relu(acc * (x[0,n]*self_w[n]) + bias[n]).
__global__ void __launch_bounds__(512)
epilogue_kernel(const float* __restrict__ x,
                const float* __restrict__ self_w,
                const float* __restrict__ bias,
                float* __restrict__ out) {
    __shared__ float tile[32][65];
    __shared__ float s_sl[32];
    __shared__ float s_b[32];
    int tid = threadIdx.x;
    int n0 = blockIdx.x * 32;

    // Load accT (float4 along b): 32 nc x 16 bq = 512 items.
    {
        const float4* acc4 = (const float4*)g_accT;
        int nc = tid >> 4, bq = tid & 15;
        int n = n0 + nc;
        float4 v = acc4[n * 16 + bq];
        tile[nc][4 * bq + 0] = v.x;
        tile[nc][4 * bq + 1] = v.y;
        tile[nc][4 * bq + 2] = v.z;
        tile[nc][4 * bq + 3] = v.w;
    }
    if (tid < 32) {
        int n = n0 + tid;
        s_sl[tid] = x[n] * self_w[n];   // x[0, n] — faithful reference quirk
        s_b[tid]  = bias[n];
    }
    __syncthreads();

    // Store: coalesced float4 writes along n. 64 b x 8 q = 512 items.
    {
        float4* out4 = (float4*)out;
        int b = tid >> 3, q = tid & 7;
        int nc = 4 * q;
        float4 r;
        r.x = fmaxf(fmaf(tile[nc + 0][b], s_sl[nc + 0], s_b[nc + 0]), 0.f);
        r.y = fmaxf(fmaf(tile[nc + 1][b], s_sl[nc + 1], s_b[nc + 1]), 0.f);
        r.z = fmaxf(fmaf(tile[nc + 2][b], s_sl[nc + 2], s_b[nc + 2]), 0.f);
        r.w = fmaxf(fmaf(tile[nc + 3][b], s_sl[nc + 3], s_b[nc + 3]), 0.f);
        out4[b * (NN / 4) + (n0 >> 2) + q] = r;
    }
}

extern "C" void kernel_launch(void* const* d_in, const int* in_sizes, int n_in,
                              void* d_out, int out_size) {
    const float* x      = (const float*)d_in[0];
    const float* adj    = (const float*)d_in[1];
    const float* w      = (const float*)d_in[2];
    const float* self_w = (const float*)d_in[3];
    const float* bias   = (const float*)d_in[4];
    const int*   src    = (const int*)d_in[5];
    const int*   dst    = (const int*)d_in[6];
    float* out = (float*)d_out;

    prep_kernel<<<TNB, 512>>>(x);
    scatter_kernel<<<EE / 256, 256>>>(adj, w, src, dst);
    epilogue_kernel<<<TNB, 512>>>(x, self_w, bias, out);
}

// round 7
// speedup vs baseline: 1.0201x; 1.0201x over previous
#include <cuda_runtime.h>

#define NN 20000
#define BB 64
#define EE 1280000
#define NTILE 625          // NN / 32 tiles of 32 n-columns
#define TPB 4              // tiles per block
#define GRID_T 157         // ceil(625 / 4)

// Scratch (allocation-free per rules).
__device__ __align__(16) float g_xT[NN * BB];    // xT[n*64 + b]
__device__ __align__(16) float g_accT[NN * BB];  // accT[n*64 + b]

// K1: smem-tiled transpose x[B,N] -> xT[N,B] + zero accT.
// 4 tiles (32n x 64b) per block; all 4 DRAM LDG.128s per thread are
// independent and front-batched (MLP=4) to hide the 577-cyc DRAM latency.
__global__ void __launch_bounds__(512)
prep_kernel(const float* __restrict__ x) {
    __shared__ float t[TPB][32][65];
    int tid = threadIdx.x;
    int t0 = blockIdx.x * TPB;

    const float4* x4 = (const float4*)x;

    // Phase A: coalesced float4 reads along n; 64 b x 8 q = 512 items/tile.
    int b = tid >> 3, q = tid & 7;
    float4 v[TPB];
    #pragma unroll
    for (int k = 0; k < TPB; k++) {
        int tt = t0 + k;
        if (tt < NTILE)
            v[k] = x4[b * (NN / 4) + tt * 8 + q];   // independent LDGs, batched
    }
    #pragma unroll
    for (int k = 0; k < TPB; k++) {
        if (t0 + k < NTILE) {
            int nc = 4 * q;
            t[k][nc + 0][b] = v[k].x;
            t[k][nc + 1][b] = v[k].y;
            t[k][nc + 2][b] = v[k].z;
            t[k][nc + 3][b] = v[k].w;
        }
    }
    __syncthreads();

    // Phase B: coalesced float4 writes along b; 32 nc x 16 bq = 512 items/tile.
    float4* xT4  = (float4*)g_xT;
    float4* acc4 = (float4*)g_accT;
    int nc = tid >> 4, bq = tid & 15;
    const float4 z = make_float4(0.f, 0.f, 0.f, 0.f);
    #pragma unroll
    for (int k = 0; k < TPB; k++) {
        int tt = t0 + k;
        if (tt < NTILE) {
            int n = tt * 32 + nc;
            float4 o;
            o.x = t[k][nc][4 * bq + 0];
            o.y = t[k][nc][4 * bq + 1];
            o.z = t[k][nc][4 * bq + 2];
            o.w = t[k][nc][4 * bq + 3];
            xT4[n * 16 + bq]  = o;
            acc4[n * 16 + bq] = z;
        }
    }
}

// K2: edge scatter, half-warp per edge (unchanged — at the LTS byte cap).
// Per edge: one LDG.128 gather from L2-resident xT + one red.global.add.v4.f32.
__global__ void scatter_kernel(const float* __restrict__ adj,
                               const float* __restrict__ w,
                               const int* __restrict__ src,
                               const int* __restrict__ dst) {
    int g = (blockIdx.x * blockDim.x + threadIdx.x) >> 5;  // warp id
    int lane = threadIdx.x & 31;
    int e = g * 32 + lane;
    if (e >= EE) return;  // EE % 32 == 0: whole warp exits together

    int   s = src[e];
    int   d = dst[e];
    float v = adj[e] * w[e];

    int half = lane >> 4;
    int ll   = lane & 15;

    const float4* xT4 = (const float4*)g_xT;

    #pragma unroll 1
    for (int j = 0; j < 16; j++) {
        int sel = 2 * j + half;
        int   sj = __shfl_sync(0xffffffffu, s, sel);
        int   dj = __shfl_sync(0xffffffffu, d, sel);
        float vj = __shfl_sync(0xffffffffu, v, sel);

        float4 xv = xT4[sj * 16 + ll];           // LDG.128, coalesced, L2-hit
        float4 r;
        r.x = vj * xv.x;  r.y = vj * xv.y;
        r.z = vj * xv.z;  r.w = vj * xv.w;

        float* accp = &g_accT[dj * 64 + 4 * ll]; // 16B-aligned
        asm volatile("red.global.add.v4.f32 [%0], {%1, %2, %3, %4};"
                     :: "l"(accp), "f"(r.x), "f"(r.y), "f"(r.z), "f"(r.w)
                     : "memory");
    }
}

// K3: epilogue. 4 tiles per block, MLP-batched L2 reads of accT, smem
// transpose, coalesced float4 stores of out = relu(acc*sl + b).
__global__ void __launch_bounds__(512)
epilogue_kernel(const float* __restrict__ x,
                const float* __restrict__ self_w,
                const float* __restrict__ bias,
                float* __restrict__ out) {
    __shared__ float tile[TPB][32][65];
    __shared__ float s_sl[TPB * 32];
    __shared__ float s_b[TPB * 32];
    int tid = threadIdx.x;
    int t0 = blockIdx.x * TPB;

    // Load accT (float4 along b); 4 independent L2-hit LDGs front-batched.
    const float4* acc4 = (const float4*)g_accT;
    int nc = tid >> 4, bq = tid & 15;
    float4 v[TPB];
    #pragma unroll
    for (int k = 0; k < TPB; k++) {
        int tt = t0 + k;
        if (tt < NTILE)
            v[k] = acc4[(tt * 32 + nc) * 16 + bq];
    }
    #pragma unroll
    for (int k = 0; k < TPB; k++) {
        if (t0 + k < NTILE) {
            tile[k][nc][4 * bq + 0] = v[k].x;
            tile[k][nc][4 * bq + 1] = v[k].y;
            tile[k][nc][4 * bq + 2] = v[k].z;
            tile[k][nc][4 * bq + 3] = v[k].w;
        }
    }
    if (tid < TPB * 32) {
        int n = t0 * 32 + tid;
        if (n < NN) {
            s_sl[tid] = x[n] * self_w[n];   // x[0, n] — faithful reference quirk
            s_b[tid]  = bias[n];
        }
    }
    __syncthreads();

    // Store: coalesced float4 writes along n; 64 b x 8 q = 512 items/tile.
    float4* out4 = (float4*)out;
    int b = tid >> 3, q = tid & 7;
    #pragma unroll
    for (int k = 0; k < TPB; k++) {
        int tt = t0 + k;
        if (tt < NTILE) {
            int ncq = 4 * q;
            int sb  = k * 32 + ncq;
            float4 r;
            r.x = fmaxf(fmaf(tile[k][ncq + 0][b], s_sl[sb + 0], s_b[sb + 0]), 0.f);
            r.y = fmaxf(fmaf(tile[k][ncq + 1][b], s_sl[sb + 1], s_b[sb + 1]), 0.f);
            r.z = fmaxf(fmaf(tile[k][ncq + 2][b], s_sl[sb + 2], s_b[sb + 2]), 0.f);
            r.w = fmaxf(fmaf(tile[k][ncq + 3][b], s_sl[sb + 3], s_b[sb + 3]), 0.f);
            out4[b * (NN / 4) + tt * 8 + q] = r;
        }
    }
}

extern "C" void kernel_launch(void* const* d_in, const int* in_sizes, int n_in,
                              void* d_out, int out_size) {
    const float* x      = (const float*)d_in[0];
    const float* adj    = (const float*)d_in[1];
    const float* w      = (const float*)d_in[2];
    const float* self_w = (const float*)d_in[3];
    const float* bias   = (const float*)d_in[4];
    const int*   src    = (const int*)d_in[5];
    const int*   dst    = (const int*)d_in[6];
    float* out = (float*)d_out;

    prep_kernel<<<GRID_T, 512>>>(x);
    scatter_kernel<<<EE / 256, 256>>>(adj, w, src, dst);
    epilogue_kernel<<<GRID_T, 512>>>(x, self_w, bias, out);
}